// round 5
// baseline (speedup 1.0000x reference)
#include <cuda_runtime.h>
#include <cuda_bf16.h>
#include <math.h>
#include <stdint.h>

typedef __nv_bfloat16 bf16;

#define SEQ 2048
#define DM  4096
#define NH  16
#define DH  256
#define DFF 16384

// GEMM tiling: CTA 128x256, BK=64, 8 warps (2x4), warp tile 64x64
#define BM 128
#define BN 256
#define BK 64
#define A_TILE_B 16384
#define B_TILE_B 32768
#define BUF_B    (2 * A_TILE_B + 2 * B_TILE_B)   // 96KB
#define GEMM_SMEM (2 * BUF_B)                    // 192KB

// ---------------------------------------------------------------------------
// Device-global scratch
// ---------------------------------------------------------------------------
__device__ bf16 g_xnh[SEQ*DM], g_xnl[SEQ*DM];
__device__ float g_v[SEQ*DM];
__device__ bf16 g_qh[SEQ*DM], g_ql[SEQ*DM], g_kh[SEQ*DM], g_kl[SEQ*DM];
__device__ bf16 g_vth[(size_t)DM*SEQ], g_vtl[(size_t)DM*SEQ];
__device__ float g_logits[(size_t)NH*SEQ*SEQ];
__device__ bf16 g_wgh[(size_t)NH*SEQ*SEQ], g_wgl[(size_t)NH*SEQ*SEQ];
__device__ bf16 g_avh[SEQ*DM], g_avl[SEQ*DM];
__device__ float g_attnout[SEQ*DM];
__device__ bf16 g_ffh[(size_t)SEQ*DFF], g_ffl[(size_t)SEQ*DFF];
__device__ float g_ropetab[SEQ * 64];
__device__ bf16 g_wqth[(size_t)DM*DM],  g_wqtl[(size_t)DM*DM];
__device__ bf16 g_wkth[(size_t)DM*DM],  g_wktl[(size_t)DM*DM];
__device__ bf16 g_wvth[(size_t)DM*DM],  g_wvtl[(size_t)DM*DM];
__device__ bf16 g_woth[(size_t)DM*DM],  g_wotl[(size_t)DM*DM];
__device__ bf16 g_w1th[(size_t)DFF*DM], g_w1tl[(size_t)DFF*DM];
__device__ bf16 g_w2th[(size_t)DM*DFF], g_w2tl[(size_t)DM*DFF];

// ---------------------------------------------------------------------------
// PTX helpers
// ---------------------------------------------------------------------------
__device__ __forceinline__ uint32_t smem_u32(const void* p) {
    uint32_t r;
    asm("{ .reg .u64 t; cvta.to.shared.u64 t, %1; cvt.u32.u64 %0, t; }" : "=r"(r) : "l"(p));
    return r;
}
__device__ __forceinline__ void cp16(uint32_t dst, const void* src) {
    asm volatile("cp.async.cg.shared.global [%0], [%1], 16;" :: "r"(dst), "l"(src));
}
#define CP_COMMIT() asm volatile("cp.async.commit_group;")
#define CP_WAIT(n)  asm volatile("cp.async.wait_group %0;" :: "n"(n))

#define LDMX4(r, a) \
    asm volatile("ldmatrix.sync.aligned.m8n8.x4.shared.b16 {%0,%1,%2,%3}, [%4];" \
        : "=r"((r)[0]), "=r"((r)[1]), "=r"((r)[2]), "=r"((r)[3]) : "r"(a))

#define MMA16816(c, a, b0, b1) \
    asm volatile("mma.sync.aligned.m16n8k16.row.col.f32.bf16.bf16.f32 " \
        "{%0,%1,%2,%3}, {%4,%5,%6,%7}, {%8,%9}, {%0,%1,%2,%3};" \
        : "+f"((c)[0]), "+f"((c)[1]), "+f"((c)[2]), "+f"((c)[3]) \
        : "r"((a)[0]), "r"((a)[1]), "r"((a)[2]), "r"((a)[3]), \
          "r"(b0), "r"(b1))

__device__ __forceinline__ void split_store(float v, bf16* ph, bf16* pl, size_t idx) {
    bf16 h = __float2bfloat16(v);
    ph[idx] = h;
    pl[idx] = __float2bfloat16(v - __bfloat162float(h));
}

// Epilogues
#define EPI_F32       0
#define EPI_SCALE     1
#define EPI_HILO      2
#define EPI_GELU_HILO 3
#define EPI_BIAS_ADD  4
#define EPI_ROPE_HILO 5
// Causal modes
#define CM_NONE   0
#define CM_LOGITS 1
#define CM_AV     2

__device__ __forceinline__ float gelu_tanh(float v) {
    const float c = 0.7978845608028654f;
    float t = tanhf(c * (v + 0.044715f * v * v * v));
    return 0.5f * v * (1.0f + t);
}

// ---------------------------------------------------------------------------
// Split-bf16 tensor-core GEMM: C[M,N] = A @ B^T
// qkv mode: blockIdx.z selects weight (q/k/v) and output; rope fused for q,k.
// ---------------------------------------------------------------------------
__global__ void __launch_bounds__(256, 1) gemm_bf16x3(
    const bf16* __restrict__ Ah, const bf16* __restrict__ Al, int lda, unsigned long long sA,
    const bf16* __restrict__ Bh, const bf16* __restrict__ Bl, int ldb, unsigned long long sB,
    int K, int epi, int cmode,
    float* __restrict__ Cf, bf16* __restrict__ Ch, bf16* __restrict__ Cl,
    int ldc, unsigned long long sC,
    const float* __restrict__ bias, const float* __restrict__ addv, float scale,
    int qkv,
    const bf16* __restrict__ Bh2, const bf16* __restrict__ Bl2,
    const bf16* __restrict__ Bh3, const bf16* __restrict__ Bl3,
    bf16* __restrict__ Ch2, bf16* __restrict__ Cl2, float* __restrict__ Cf3,
    const float* __restrict__ ropetab)
{
    int bm = blockIdx.y * BM;
    int bn = blockIdx.x * BN;
    if (cmode == CM_LOGITS && bn >= bm + BM) return;

    if (qkv) {
        int z = blockIdx.z;
        if (z == 1)      { Bh = Bh2; Bl = Bl2; Ch = Ch2; Cl = Cl2; }
        else if (z == 2) { Bh = Bh3; Bl = Bl3; Cf = Cf3; }
        epi = (z == 2) ? EPI_F32 : EPI_ROPE_HILO;
    } else {
        Ah += (size_t)blockIdx.z * sA;  Al += (size_t)blockIdx.z * sA;
        Bh += (size_t)blockIdx.z * sB;  Bl += (size_t)blockIdx.z * sB;
    }
    size_t coff = qkv ? 0 : (size_t)blockIdx.z * sC;

    extern __shared__ char smem[];
    uint32_t sb = smem_u32(smem);
    int tid = threadIdx.x;
    int wid = tid >> 5, lane = tid & 31;
    int warp_m = wid >> 2, warp_n = wid & 3;

    int a_r  = ((lane >> 3) & 1) * 8 + (lane & 7);
    int a_cb = (lane >> 4) * 16;
    int b_r  = (lane >> 4) * 8 + (lane & 7);
    int b_cb = ((lane >> 3) & 1) * 16;

    float acc[4][8][4];
    #pragma unroll
    for (int i = 0; i < 4; i++)
        #pragma unroll
        for (int j = 0; j < 8; j++)
            #pragma unroll
            for (int e = 0; e < 4; e++) acc[i][j][e] = 0.f;

#define LOAD_CHUNK(k0, bufb) do {                                              \
        _Pragma("unroll")                                                      \
        for (int t = 0; t < 4; t++) {                                          \
            int ch = tid + t * 256;                                            \
            int row = ch >> 3, c = ch & 7;                                     \
            uint32_t off = row * 128 + ((c * 16) ^ ((row * 16) & 0x70));       \
            cp16((bufb) + off,            Ah + (size_t)(bm + row) * lda + (k0) + c * 8); \
            cp16((bufb) + A_TILE_B + off, Al + (size_t)(bm + row) * lda + (k0) + c * 8); \
        }                                                                      \
        _Pragma("unroll")                                                      \
        for (int t = 0; t < 8; t++) {                                          \
            int ch = tid + t * 256;                                            \
            int row = ch >> 3, c = ch & 7;                                     \
            uint32_t off = row * 128 + ((c * 16) ^ ((row * 16) & 0x70));       \
            cp16((bufb) + 2*A_TILE_B + off,            Bh + (size_t)(bn + row) * ldb + (k0) + c * 8); \
            cp16((bufb) + 2*A_TILE_B + B_TILE_B + off, Bl + (size_t)(bn + row) * ldb + (k0) + c * 8); \
        }                                                                      \
    } while (0)

    int Keff = (cmode == CM_AV) ? (bm + BM) : K;
    int nk = Keff / BK;

    LOAD_CHUNK(0, sb);
    CP_COMMIT();

    for (int i = 0; i < nk; i++) {
        uint32_t bufb = sb + (uint32_t)(i & 1) * BUF_B;
        if (i + 1 < nk) {
            uint32_t nb = sb + (uint32_t)((i + 1) & 1) * BUF_B;
            LOAD_CHUNK((i + 1) * BK, nb);
            CP_COMMIT();
            CP_WAIT(1);
        } else {
            CP_WAIT(0);
        }
        __syncthreads();

        #pragma unroll
        for (int ks = 0; ks < 4; ks++) {
            uint32_t ahf[4][4], alf[4][4];
            #pragma unroll
            for (int mt = 0; mt < 4; mt++) {
                int row = warp_m * 64 + mt * 16 + a_r;
                uint32_t cb = ks * 32 + a_cb;
                uint32_t off = row * 128 + (cb ^ ((row * 16) & 0x70));
                LDMX4(ahf[mt], bufb + off);
                LDMX4(alf[mt], bufb + A_TILE_B + off);
            }
            #pragma unroll
            for (int p = 0; p < 4; p++) {
                int row = warp_n * 64 + p * 16 + b_r;
                uint32_t cb = ks * 32 + b_cb;
                uint32_t off = row * 128 + (cb ^ ((row * 16) & 0x70));
                uint32_t rh[4], rl[4];
                LDMX4(rh, bufb + 2 * A_TILE_B + off);
                LDMX4(rl, bufb + 2 * A_TILE_B + B_TILE_B + off);
                #pragma unroll
                for (int mt = 0; mt < 4; mt++) {
                    MMA16816(acc[mt][2*p],   ahf[mt], rh[0], rh[1]);
                    MMA16816(acc[mt][2*p],   ahf[mt], rl[0], rl[1]);
                    MMA16816(acc[mt][2*p],   alf[mt], rh[0], rh[1]);
                    MMA16816(acc[mt][2*p+1], ahf[mt], rh[2], rh[3]);
                    MMA16816(acc[mt][2*p+1], ahf[mt], rl[2], rl[3]);
                    MMA16816(acc[mt][2*p+1], alf[mt], rh[2], rh[3]);
                }
            }
        }
        __syncthreads();
    }
#undef LOAD_CHUNK

    // Epilogue
    int g = lane >> 2, tg = lane & 3;
    #pragma unroll
    for (int mt = 0; mt < 4; mt++) {
        #pragma unroll
        for (int nt = 0; nt < 8; nt++) {
            int row0 = bm + warp_m * 64 + mt * 16 + g;
            int col  = bn + warp_n * 64 + nt * 8 + tg * 2;
            float* a = acc[mt][nt];
            #pragma unroll
            for (int half = 0; half < 2; half++) {
                int row = row0 + half * 8;
                float v0 = a[half * 2 + 0], v1 = a[half * 2 + 1];
                size_t idx = coff + (size_t)row * ldc + col;
                if (epi == EPI_F32) {
                    *(float2*)(Cf + idx) = make_float2(v0, v1);
                } else if (epi == EPI_SCALE) {
                    *(float2*)(Cf + idx) = make_float2(v0 * scale, v1 * scale);
                } else if (epi == EPI_HILO) {
                    bf16 h0 = __float2bfloat16(v0), h1 = __float2bfloat16(v1);
                    __nv_bfloat162 hp; hp.x = h0; hp.y = h1;
                    __nv_bfloat162 lp;
                    lp.x = __float2bfloat16(v0 - __bfloat162float(h0));
                    lp.y = __float2bfloat16(v1 - __bfloat162float(h1));
                    *(__nv_bfloat162*)(Ch + idx) = hp;
                    *(__nv_bfloat162*)(Cl + idx) = lp;
                } else if (epi == EPI_GELU_HILO) {
                    float g0 = gelu_tanh(v0 + bias[col]);
                    float g1 = gelu_tanh(v1 + bias[col + 1]);
                    bf16 h0 = __float2bfloat16(g0), h1 = __float2bfloat16(g1);
                    __nv_bfloat162 hp; hp.x = h0; hp.y = h1;
                    __nv_bfloat162 lp;
                    lp.x = __float2bfloat16(g0 - __bfloat162float(h0));
                    lp.y = __float2bfloat16(g1 - __bfloat162float(h1));
                    *(__nv_bfloat162*)(Ch + idx) = hp;
                    *(__nv_bfloat162*)(Cl + idx) = lp;
                } else if (epi == EPI_ROPE_HILO) {
                    int d = col & (DH - 1);
                    if (d < 64) {
                        float s = ropetab[row * 64 + d];
                        float c = ropetab[row * 64 + d + 1];
                        float n0 = v0 * c - v1 * s;
                        float n1 = v1 * c + v0 * s;
                        v0 = n0; v1 = n1;
                    }
                    bf16 h0 = __float2bfloat16(v0), h1 = __float2bfloat16(v1);
                    __nv_bfloat162 hp; hp.x = h0; hp.y = h1;
                    __nv_bfloat162 lp;
                    lp.x = __float2bfloat16(v0 - __bfloat162float(h0));
                    lp.y = __float2bfloat16(v1 - __bfloat162float(h1));
                    *(__nv_bfloat162*)(Ch + idx) = hp;
                    *(__nv_bfloat162*)(Cl + idx) = lp;
                } else { // EPI_BIAS_ADD
                    float2 av = *(const float2*)(addv + idx);
                    *(float2*)(Cf + idx) = make_float2(v0 + bias[col] + av.x,
                                                       v1 + bias[col + 1] + av.y);
                }
            }
        }
    }
}

// ---------------------------------------------------------------------------
// RoPE sin/cos table: tab[t*64 + 2i] = sin(t*inv_i), [.. + 1] = cos (fp64)
// ---------------------------------------------------------------------------
__global__ void ropetab_kernel(float* __restrict__ tab)
{
    int idx = blockIdx.x * 256 + threadIdx.x;
    if (idx >= SEQ * 32) return;
    int i = idx & 31, t = idx >> 5;
    double inv = exp(-(double)i * (9.210340371976184 / 32.0));
    double s, c;
    sincos((double)t * inv, &s, &c);
    tab[t * 64 + 2 * i]     = (float)s;
    tab[t * 64 + 2 * i + 1] = (float)c;
}

// ---------------------------------------------------------------------------
// LayerNorm -> hi/lo bf16
// ---------------------------------------------------------------------------
__global__ void ln_kernel(const float* __restrict__ x,
                          const float* __restrict__ scale,
                          const float* __restrict__ offset,
                          bf16* __restrict__ xh, bf16* __restrict__ xl)
{
    __shared__ float red[256];
    int row = blockIdx.x;
    int tid = threadIdx.x;
    const float* xr = x + (size_t)row * DM;

    float s = 0.f;
    for (int i = tid; i < DM; i += 256) s += xr[i];
    red[tid] = s; __syncthreads();
    for (int o = 128; o > 0; o >>= 1) { if (tid < o) red[tid] += red[tid + o]; __syncthreads(); }
    float mean = red[0] / (float)DM;
    __syncthreads();

    float v = 0.f;
    for (int i = tid; i < DM; i += 256) { float d = xr[i] - mean; v += d * d; }
    red[tid] = v; __syncthreads();
    for (int o = 128; o > 0; o >>= 1) { if (tid < o) red[tid] += red[tid + o]; __syncthreads(); }
    float r = rsqrtf(red[0] / (float)DM + 1e-5f);

    for (int i = tid; i < DM; i += 256) {
        float y = scale[i] * r * (xr[i] - mean) + offset[i];
        split_store(y, xh, xl, (size_t)row * DM + i);
    }
}

// ---------------------------------------------------------------------------
// Transpose + hi/lo convert v2: 64x64 tiles, float4 loads, bf162 stores
// in[R][C] fp32 -> out[C][R] hi/lo bf16.  Requires R,C % 64 == 0.
// ---------------------------------------------------------------------------
__global__ void transcvt_kernel(const float* __restrict__ in, int R, int C,
                                bf16* __restrict__ oh, bf16* __restrict__ ol)
{
    __shared__ float t[64][65];
    int c0 = blockIdx.x * 64;
    int r0 = blockIdx.y * 64;
    int tid = threadIdx.x;
    #pragma unroll
    for (int p = 0; p < 4; p++) {
        int f = tid + p * 256;
        int row = f >> 4, c4 = (f & 15) * 4;
        float4 v = *(const float4*)(in + (size_t)(r0 + row) * C + c0 + c4);
        t[row][c4 + 0] = v.x; t[row][c4 + 1] = v.y;
        t[row][c4 + 2] = v.z; t[row][c4 + 3] = v.w;
    }
    __syncthreads();
    #pragma unroll
    for (int p = 0; p < 8; p++) {
        int w = tid + p * 256;
        int c = w >> 5, rp = (w & 31) * 2;
        float v0 = t[rp][c], v1 = t[rp + 1][c];
        size_t idx = (size_t)(c0 + c) * R + r0 + rp;
        bf16 h0 = __float2bfloat16(v0), h1 = __float2bfloat16(v1);
        __nv_bfloat162 hp; hp.x = h0; hp.y = h1;
        __nv_bfloat162 lp;
        lp.x = __float2bfloat16(v0 - __bfloat162float(h0));
        lp.y = __float2bfloat16(v1 - __bfloat162float(h1));
        *(__nv_bfloat162*)(oh + idx) = hp;
        *(__nv_bfloat162*)(ol + idx) = lp;
    }
}

// ---------------------------------------------------------------------------
// Causal softmax: row cached in smem, zero-fill to 128-block end
// ---------------------------------------------------------------------------
__global__ void softmax_kernel(const float* __restrict__ logits,
                               const float* __restrict__ attn_bias,
                               bf16* __restrict__ wh, bf16* __restrict__ wl)
{
    __shared__ float rowbuf[SEQ];
    __shared__ float red[256];
    int t = blockIdx.x;
    int h = blockIdx.y;
    int tid = threadIdx.x;
    size_t base = ((size_t)h * SEQ + t) * SEQ;
    const float* brow = attn_bias + (size_t)t * SEQ;
    int n = t + 1;
    int blockend = ((t >> 7) + 1) << 7;

    float m = -INFINITY;
    for (int T = tid; T < n; T += 256) {
        float l = logits[base + T] + brow[T];
        rowbuf[T] = l;
        m = fmaxf(m, l);
    }
    red[tid] = m; __syncthreads();
    for (int o = 128; o > 0; o >>= 1) { if (tid < o) red[tid] = fmaxf(red[tid], red[tid + o]); __syncthreads(); }
    m = red[0]; __syncthreads();

    float s = 0.f;
    for (int T = tid; T < n; T += 256) {
        float e = expf(rowbuf[T] - m);
        rowbuf[T] = e;
        s += e;
    }
    red[tid] = s; __syncthreads();
    for (int o = 128; o > 0; o >>= 1) { if (tid < o) red[tid] += red[tid + o]; __syncthreads(); }
    float inv = 1.0f / red[0];

    for (int T = tid; T < n; T += 256)
        split_store(rowbuf[T] * inv, wh, wl, base + T);
    for (int T = n + tid; T < blockend; T += 256) {
        wh[base + T] = __float2bfloat16(0.f);
        wl[base + T] = __float2bfloat16(0.f);
    }
}

// ---------------------------------------------------------------------------
// Launcher
// ---------------------------------------------------------------------------
extern "C" void kernel_launch(void* const* d_in, const int* in_sizes, int n_in,
                              void* d_out, int out_size)
{
    const float* x         = (const float*)d_in[0];
    const float* attn_bias = (const float*)d_in[1];
    const float* ln_scale  = (const float*)d_in[2];
    const float* ln_offset = (const float*)d_in[3];
    const float* wq        = (const float*)d_in[4];
    const float* wk        = (const float*)d_in[5];
    const float* wv        = (const float*)d_in[6];
    const float* wo        = (const float*)d_in[7];
    const float* w1        = (const float*)d_in[8];
    const float* b1        = (const float*)d_in[9];
    const float* w2        = (const float*)d_in[10];
    const float* b2        = (const float*)d_in[11];
    float* out = (float*)d_out;

    cudaFuncSetAttribute(gemm_bf16x3, cudaFuncAttributeMaxDynamicSharedMemorySize, GEMM_SMEM);

    bf16 *xnh, *xnl, *qh, *ql, *kh, *kl, *vth, *vtl, *wgh, *wgl, *avh, *avl, *ffh, *ffl;
    bf16 *wqth, *wqtl, *wkth, *wktl, *wvth, *wvtl, *woth, *wotl, *w1th, *w1tl, *w2th, *w2tl;
    float *v, *logits, *attnout, *ropetab;
    cudaGetSymbolAddress((void**)&xnh, g_xnh);   cudaGetSymbolAddress((void**)&xnl, g_xnl);
    cudaGetSymbolAddress((void**)&v, g_v);
    cudaGetSymbolAddress((void**)&qh, g_qh);     cudaGetSymbolAddress((void**)&ql, g_ql);
    cudaGetSymbolAddress((void**)&kh, g_kh);     cudaGetSymbolAddress((void**)&kl, g_kl);
    cudaGetSymbolAddress((void**)&vth, g_vth);   cudaGetSymbolAddress((void**)&vtl, g_vtl);
    cudaGetSymbolAddress((void**)&logits, g_logits);
    cudaGetSymbolAddress((void**)&wgh, g_wgh);   cudaGetSymbolAddress((void**)&wgl, g_wgl);
    cudaGetSymbolAddress((void**)&avh, g_avh);   cudaGetSymbolAddress((void**)&avl, g_avl);
    cudaGetSymbolAddress((void**)&attnout, g_attnout);
    cudaGetSymbolAddress((void**)&ffh, g_ffh);   cudaGetSymbolAddress((void**)&ffl, g_ffl);
    cudaGetSymbolAddress((void**)&ropetab, g_ropetab);
    cudaGetSymbolAddress((void**)&wqth, g_wqth); cudaGetSymbolAddress((void**)&wqtl, g_wqtl);
    cudaGetSymbolAddress((void**)&wkth, g_wkth); cudaGetSymbolAddress((void**)&wktl, g_wktl);
    cudaGetSymbolAddress((void**)&wvth, g_wvth); cudaGetSymbolAddress((void**)&wvtl, g_wvtl);
    cudaGetSymbolAddress((void**)&woth, g_woth); cudaGetSymbolAddress((void**)&wotl, g_wotl);
    cudaGetSymbolAddress((void**)&w1th, g_w1th); cudaGetSymbolAddress((void**)&w1tl, g_w1tl);
    cudaGetSymbolAddress((void**)&w2th, g_w2th); cudaGetSymbolAddress((void**)&w2tl, g_w2tl);

    // rope table + weight prep
    ropetab_kernel<<<(SEQ * 32 + 255) / 256, 256>>>(ropetab);
    transcvt_kernel<<<dim3(DM / 64, DM / 64), 256>>>(wq, DM, DM, wqth, wqtl);
    transcvt_kernel<<<dim3(DM / 64, DM / 64), 256>>>(wk, DM, DM, wkth, wktl);
    transcvt_kernel<<<dim3(DM / 64, DM / 64), 256>>>(wv, DM, DM, wvth, wvtl);
    transcvt_kernel<<<dim3(DM / 64, DM / 64), 256>>>(wo, DM, DM, woth, wotl);
    transcvt_kernel<<<dim3(DFF / 64, DM / 64), 256>>>(w1, DM, DFF, w1th, w1tl);
    transcvt_kernel<<<dim3(DM / 64, DFF / 64), 256>>>(w2, DFF, DM, w2th, w2tl);

    ln_kernel<<<SEQ, 256>>>(x, ln_scale, ln_offset, xnh, xnl);

    // fused QKV (z=0:q +rope, z=1:k +rope, z=2:v fp32)
    dim3 gQKV(DM / BN, SEQ / BM, 3);
    gemm_bf16x3<<<gQKV, 256, GEMM_SMEM>>>(xnh, xnl, DM, 0, wqth, wqtl, DM, 0, DM,
                                          EPI_F32, CM_NONE, nullptr, qh, ql, DM, 0,
                                          nullptr, nullptr, 1.f,
                                          1, wkth, wktl, wvth, wvtl, kh, kl, v, ropetab);

    // v transpose: v[SEQ][DM] -> vt[DM][SEQ] hi/lo
    transcvt_kernel<<<dim3(DM / 64, SEQ / 64), 256>>>(v, SEQ, DM, vth, vtl);

    // logits[h] = q_h @ k_h^T / 16 (skip fully masked tiles)
    dim3 gLog(SEQ / BN, SEQ / BM, NH);
    gemm_bf16x3<<<gLog, 256, GEMM_SMEM>>>(qh, ql, DM, DH, kh, kl, DM, DH, DH,
                                          EPI_SCALE, CM_LOGITS, logits, nullptr, nullptr, SEQ, (unsigned long long)SEQ * SEQ,
                                          nullptr, nullptr, 0.0625f,
                                          0, nullptr, nullptr, nullptr, nullptr, nullptr, nullptr, nullptr, nullptr);

    softmax_kernel<<<dim3(SEQ, NH), 256>>>(logits, attn_bias, wgh, wgl);

    // attn_vec[h] = W_h @ v_h  (variable K)
    dim3 gAV(DH / BN, SEQ / BM, NH);
    gemm_bf16x3<<<gAV, 256, GEMM_SMEM>>>(wgh, wgl, SEQ, (unsigned long long)SEQ * SEQ,
                                         vth, vtl, SEQ, (unsigned long long)DH * SEQ, SEQ,
                                         EPI_HILO, CM_AV, nullptr, avh, avl, DM, DH,
                                         nullptr, nullptr, 1.f,
                                         0, nullptr, nullptr, nullptr, nullptr, nullptr, nullptr, nullptr, nullptr);

    dim3 gProj(DM / BN, SEQ / BM, 1);
    gemm_bf16x3<<<gProj, 256, GEMM_SMEM>>>(avh, avl, DM, 0, woth, wotl, DM, 0, DM,
                                           EPI_F32, CM_NONE, attnout, nullptr, nullptr, DM, 0,
                                           nullptr, nullptr, 1.f,
                                           0, nullptr, nullptr, nullptr, nullptr, nullptr, nullptr, nullptr, nullptr);

    dim3 gFF1(DFF / BN, SEQ / BM, 1);
    gemm_bf16x3<<<gFF1, 256, GEMM_SMEM>>>(xnh, xnl, DM, 0, w1th, w1tl, DM, 0, DM,
                                          EPI_GELU_HILO, CM_NONE, nullptr, ffh, ffl, DFF, 0,
                                          b1, nullptr, 1.f,
                                          0, nullptr, nullptr, nullptr, nullptr, nullptr, nullptr, nullptr, nullptr);

    dim3 gFF2(DM / BN, SEQ / BM, 1);
    gemm_bf16x3<<<gFF2, 256, GEMM_SMEM>>>(ffh, ffl, DFF, 0, w2th, w2tl, DFF, 0, DFF,
                                          EPI_BIAS_ADD, CM_NONE, out, nullptr, nullptr, DM, 0,
                                          b2, attnout, 1.f,
                                          0, nullptr, nullptr, nullptr, nullptr, nullptr, nullptr, nullptr, nullptr);
}

// round 6
// speedup vs baseline: 1.0026x; 1.0026x over previous
#include <cuda_runtime.h>
#include <cuda_bf16.h>
#include <math.h>
#include <stdint.h>

typedef __nv_bfloat16 bf16;

#define SEQ 2048
#define DM  4096
#define NH  16
#define DH  256
#define DFF 16384

// GEMM tiling: CTA 128x256, BK=64, 8 warps (2x4), warp tile 64x64
#define BM 128
#define BN 256
#define BK 64
#define A_TILE_B 16384
#define B_TILE_B 32768
#define BUF_B    (2 * A_TILE_B + 2 * B_TILE_B)   // 96KB
#define GEMM_SMEM (2 * BUF_B)                    // 192KB

// ---------------------------------------------------------------------------
// Device-global scratch
// ---------------------------------------------------------------------------
__device__ bf16 g_xnh[SEQ*DM], g_xnl[SEQ*DM];
__device__ float g_v[SEQ*DM];
__device__ bf16 g_qh[SEQ*DM], g_ql[SEQ*DM], g_kh[SEQ*DM], g_kl[SEQ*DM];
__device__ bf16 g_vth[(size_t)DM*SEQ], g_vtl[(size_t)DM*SEQ];
__device__ float g_logits[(size_t)NH*SEQ*SEQ];
__device__ bf16 g_wgh[(size_t)NH*SEQ*SEQ], g_wgl[(size_t)NH*SEQ*SEQ];
__device__ bf16 g_avh[SEQ*DM], g_avl[SEQ*DM];
__device__ float g_attnout[SEQ*DM];
__device__ bf16 g_ffh[(size_t)SEQ*DFF], g_ffl[(size_t)SEQ*DFF];
__device__ float g_ropetab[SEQ * 64];
__device__ bf16 g_wqth[(size_t)DM*DM],  g_wqtl[(size_t)DM*DM];
__device__ bf16 g_wkth[(size_t)DM*DM],  g_wktl[(size_t)DM*DM];
__device__ bf16 g_wvth[(size_t)DM*DM],  g_wvtl[(size_t)DM*DM];
__device__ bf16 g_woth[(size_t)DM*DM],  g_wotl[(size_t)DM*DM];
__device__ bf16 g_w1th[(size_t)DFF*DM], g_w1tl[(size_t)DFF*DM];
__device__ bf16 g_w2th[(size_t)DM*DFF], g_w2tl[(size_t)DM*DFF];

// ---------------------------------------------------------------------------
// PTX helpers
// ---------------------------------------------------------------------------
__device__ __forceinline__ uint32_t smem_u32(const void* p) {
    uint32_t r;
    asm("{ .reg .u64 t; cvta.to.shared.u64 t, %1; cvt.u32.u64 %0, t; }" : "=r"(r) : "l"(p));
    return r;
}
__device__ __forceinline__ void cp16(uint32_t dst, const void* src) {
    asm volatile("cp.async.cg.shared.global [%0], [%1], 16;" :: "r"(dst), "l"(src));
}
#define CP_COMMIT() asm volatile("cp.async.commit_group;")
#define CP_WAIT(n)  asm volatile("cp.async.wait_group %0;" :: "n"(n))

#define LDMX4(r, a) \
    asm volatile("ldmatrix.sync.aligned.m8n8.x4.shared.b16 {%0,%1,%2,%3}, [%4];" \
        : "=r"((r)[0]), "=r"((r)[1]), "=r"((r)[2]), "=r"((r)[3]) : "r"(a))

#define MMA16816(c, a, b0, b1) \
    asm volatile("mma.sync.aligned.m16n8k16.row.col.f32.bf16.bf16.f32 " \
        "{%0,%1,%2,%3}, {%4,%5,%6,%7}, {%8,%9}, {%0,%1,%2,%3};" \
        : "+f"((c)[0]), "+f"((c)[1]), "+f"((c)[2]), "+f"((c)[3]) \
        : "r"((a)[0]), "r"((a)[1]), "r"((a)[2]), "r"((a)[3]), \
          "r"(b0), "r"(b1))

__device__ __forceinline__ void split_store(float v, bf16* ph, bf16* pl, size_t idx) {
    bf16 h = __float2bfloat16(v);
    ph[idx] = h;
    pl[idx] = __float2bfloat16(v - __bfloat162float(h));
}

// Epilogues
#define EPI_F32       0
#define EPI_SCALE     1
#define EPI_HILO      2
#define EPI_GELU_HILO 3
#define EPI_BIAS_ADD  4
#define EPI_ROPE_HILO 5
// Causal modes
#define CM_NONE   0
#define CM_LOGITS 1
#define CM_AV     2

__device__ __forceinline__ float gelu_tanh(float v) {
    const float c = 0.7978845608028654f;
    float t = tanhf(c * (v + 0.044715f * v * v * v));
    return 0.5f * v * (1.0f + t);
}

// ---------------------------------------------------------------------------
// Split-bf16 tensor-core GEMM: C[M,N] = A @ B^T
// qkv mode: blockIdx.z selects weight (q/k/v) and output; rope fused for q,k.
// ---------------------------------------------------------------------------
__global__ void __launch_bounds__(256, 1) gemm_bf16x3(
    const bf16* __restrict__ Ah, const bf16* __restrict__ Al, int lda, unsigned long long sA,
    const bf16* __restrict__ Bh, const bf16* __restrict__ Bl, int ldb, unsigned long long sB,
    int K, int epi, int cmode,
    float* __restrict__ Cf, bf16* __restrict__ Ch, bf16* __restrict__ Cl,
    int ldc, unsigned long long sC,
    const float* __restrict__ bias, const float* __restrict__ addv, float scale,
    int qkv,
    const bf16* __restrict__ Bh2, const bf16* __restrict__ Bl2,
    const bf16* __restrict__ Bh3, const bf16* __restrict__ Bl3,
    bf16* __restrict__ Ch2, bf16* __restrict__ Cl2, float* __restrict__ Cf3,
    const float* __restrict__ ropetab)
{
    int bm = blockIdx.y * BM;
    int bn = blockIdx.x * BN;
    if (cmode == CM_LOGITS && bn >= bm + BM) return;

    if (qkv) {
        int z = blockIdx.z;
        if (z == 1)      { Bh = Bh2; Bl = Bl2; Ch = Ch2; Cl = Cl2; }
        else if (z == 2) { Bh = Bh3; Bl = Bl3; Cf = Cf3; }
        epi = (z == 2) ? EPI_F32 : EPI_ROPE_HILO;
    } else {
        Ah += (size_t)blockIdx.z * sA;  Al += (size_t)blockIdx.z * sA;
        Bh += (size_t)blockIdx.z * sB;  Bl += (size_t)blockIdx.z * sB;
    }
    size_t coff = qkv ? 0 : (size_t)blockIdx.z * sC;

    extern __shared__ char smem[];
    uint32_t sb = smem_u32(smem);
    int tid = threadIdx.x;
    int wid = tid >> 5, lane = tid & 31;
    int warp_m = wid >> 2, warp_n = wid & 3;

    int a_r  = ((lane >> 3) & 1) * 8 + (lane & 7);
    int a_cb = (lane >> 4) * 16;
    int b_r  = (lane >> 4) * 8 + (lane & 7);
    int b_cb = ((lane >> 3) & 1) * 16;

    float acc[4][8][4];
    #pragma unroll
    for (int i = 0; i < 4; i++)
        #pragma unroll
        for (int j = 0; j < 8; j++)
            #pragma unroll
            for (int e = 0; e < 4; e++) acc[i][j][e] = 0.f;

#define LOAD_CHUNK(k0, bufb) do {                                              \
        _Pragma("unroll")                                                      \
        for (int t = 0; t < 4; t++) {                                          \
            int ch = tid + t * 256;                                            \
            int row = ch >> 3, c = ch & 7;                                     \
            uint32_t off = row * 128 + ((c * 16) ^ ((row * 16) & 0x70));       \
            cp16((bufb) + off,            Ah + (size_t)(bm + row) * lda + (k0) + c * 8); \
            cp16((bufb) + A_TILE_B + off, Al + (size_t)(bm + row) * lda + (k0) + c * 8); \
        }                                                                      \
        _Pragma("unroll")                                                      \
        for (int t = 0; t < 8; t++) {                                          \
            int ch = tid + t * 256;                                            \
            int row = ch >> 3, c = ch & 7;                                     \
            uint32_t off = row * 128 + ((c * 16) ^ ((row * 16) & 0x70));       \
            cp16((bufb) + 2*A_TILE_B + off,            Bh + (size_t)(bn + row) * ldb + (k0) + c * 8); \
            cp16((bufb) + 2*A_TILE_B + B_TILE_B + off, Bl + (size_t)(bn + row) * ldb + (k0) + c * 8); \
        }                                                                      \
    } while (0)

    int Keff = (cmode == CM_AV) ? (bm + BM) : K;
    int nk = Keff / BK;

    LOAD_CHUNK(0, sb);
    CP_COMMIT();

    for (int i = 0; i < nk; i++) {
        uint32_t bufb = sb + (uint32_t)(i & 1) * BUF_B;
        if (i + 1 < nk) {
            uint32_t nb = sb + (uint32_t)((i + 1) & 1) * BUF_B;
            LOAD_CHUNK((i + 1) * BK, nb);
            CP_COMMIT();
            CP_WAIT(1);
        } else {
            CP_WAIT(0);
        }
        __syncthreads();

        #pragma unroll
        for (int ks = 0; ks < 4; ks++) {
            uint32_t ahf[4][4], alf[4][4];
            #pragma unroll
            for (int mt = 0; mt < 4; mt++) {
                int row = warp_m * 64 + mt * 16 + a_r;
                uint32_t cb = ks * 32 + a_cb;
                uint32_t off = row * 128 + (cb ^ ((row * 16) & 0x70));
                LDMX4(ahf[mt], bufb + off);
                LDMX4(alf[mt], bufb + A_TILE_B + off);
            }
            uint32_t bhf[8][2], blf[8][2];
            #pragma unroll
            for (int p = 0; p < 4; p++) {
                int row = warp_n * 64 + p * 16 + b_r;
                uint32_t cb = ks * 32 + b_cb;
                uint32_t off = row * 128 + (cb ^ ((row * 16) & 0x70));
                uint32_t r[4];
                LDMX4(r, bufb + 2 * A_TILE_B + off);
                bhf[2*p][0] = r[0]; bhf[2*p][1] = r[1];
                bhf[2*p+1][0] = r[2]; bhf[2*p+1][1] = r[3];
                LDMX4(r, bufb + 2 * A_TILE_B + B_TILE_B + off);
                blf[2*p][0] = r[0]; blf[2*p][1] = r[1];
                blf[2*p+1][0] = r[2]; blf[2*p+1][1] = r[3];
            }
            #pragma unroll
            for (int mt = 0; mt < 4; mt++)
                #pragma unroll
                for (int nt = 0; nt < 8; nt++) {
                    MMA16816(acc[mt][nt], ahf[mt], bhf[nt][0], bhf[nt][1]);
                    MMA16816(acc[mt][nt], ahf[mt], blf[nt][0], blf[nt][1]);
                    MMA16816(acc[mt][nt], alf[mt], bhf[nt][0], bhf[nt][1]);
                }
        }
        __syncthreads();
    }
#undef LOAD_CHUNK

    // Epilogue
    int g = lane >> 2, tg = lane & 3;
    #pragma unroll
    for (int mt = 0; mt < 4; mt++) {
        #pragma unroll
        for (int nt = 0; nt < 8; nt++) {
            int row0 = bm + warp_m * 64 + mt * 16 + g;
            int col  = bn + warp_n * 64 + nt * 8 + tg * 2;
            float* a = acc[mt][nt];
            #pragma unroll
            for (int half = 0; half < 2; half++) {
                int row = row0 + half * 8;
                float v0 = a[half * 2 + 0], v1 = a[half * 2 + 1];
                size_t idx = coff + (size_t)row * ldc + col;
                if (epi == EPI_F32) {
                    *(float2*)(Cf + idx) = make_float2(v0, v1);
                } else if (epi == EPI_SCALE) {
                    *(float2*)(Cf + idx) = make_float2(v0 * scale, v1 * scale);
                } else if (epi == EPI_HILO) {
                    bf16 h0 = __float2bfloat16(v0), h1 = __float2bfloat16(v1);
                    __nv_bfloat162 hp; hp.x = h0; hp.y = h1;
                    __nv_bfloat162 lp;
                    lp.x = __float2bfloat16(v0 - __bfloat162float(h0));
                    lp.y = __float2bfloat16(v1 - __bfloat162float(h1));
                    *(__nv_bfloat162*)(Ch + idx) = hp;
                    *(__nv_bfloat162*)(Cl + idx) = lp;
                } else if (epi == EPI_GELU_HILO) {
                    float g0 = gelu_tanh(v0 + bias[col]);
                    float g1 = gelu_tanh(v1 + bias[col + 1]);
                    bf16 h0 = __float2bfloat16(g0), h1 = __float2bfloat16(g1);
                    __nv_bfloat162 hp; hp.x = h0; hp.y = h1;
                    __nv_bfloat162 lp;
                    lp.x = __float2bfloat16(g0 - __bfloat162float(h0));
                    lp.y = __float2bfloat16(g1 - __bfloat162float(h1));
                    *(__nv_bfloat162*)(Ch + idx) = hp;
                    *(__nv_bfloat162*)(Cl + idx) = lp;
                } else if (epi == EPI_ROPE_HILO) {
                    int d = col & (DH - 1);
                    if (d < 64) {
                        float s = ropetab[row * 64 + d];
                        float c = ropetab[row * 64 + d + 1];
                        float n0 = v0 * c - v1 * s;
                        float n1 = v1 * c + v0 * s;
                        v0 = n0; v1 = n1;
                    }
                    bf16 h0 = __float2bfloat16(v0), h1 = __float2bfloat16(v1);
                    __nv_bfloat162 hp; hp.x = h0; hp.y = h1;
                    __nv_bfloat162 lp;
                    lp.x = __float2bfloat16(v0 - __bfloat162float(h0));
                    lp.y = __float2bfloat16(v1 - __bfloat162float(h1));
                    *(__nv_bfloat162*)(Ch + idx) = hp;
                    *(__nv_bfloat162*)(Cl + idx) = lp;
                } else { // EPI_BIAS_ADD
                    float2 av = *(const float2*)(addv + idx);
                    *(float2*)(Cf + idx) = make_float2(v0 + bias[col] + av.x,
                                                       v1 + bias[col + 1] + av.y);
                }
            }
        }
    }
}

// ---------------------------------------------------------------------------
// RoPE sin/cos table (fp64): tab[t*64+2i]=sin, tab[t*64+2i+1]=cos
// ---------------------------------------------------------------------------
__global__ void ropetab_kernel(float* __restrict__ tab)
{
    int idx = blockIdx.x * 256 + threadIdx.x;
    if (idx >= SEQ * 32) return;
    int i = idx & 31, t = idx >> 5;
    double inv = exp(-(double)i * (9.210340371976184 / 32.0));
    double s, c;
    sincos((double)t * inv, &s, &c);
    tab[t * 64 + 2 * i]     = (float)s;
    tab[t * 64 + 2 * i + 1] = (float)c;
}

// ---------------------------------------------------------------------------
// LayerNorm -> hi/lo bf16
// ---------------------------------------------------------------------------
__global__ void ln_kernel(const float* __restrict__ x,
                          const float* __restrict__ scale,
                          const float* __restrict__ offset,
                          bf16* __restrict__ xh, bf16* __restrict__ xl)
{
    __shared__ float red[256];
    int row = blockIdx.x;
    int tid = threadIdx.x;
    const float* xr = x + (size_t)row * DM;

    float s = 0.f;
    for (int i = tid; i < DM; i += 256) s += xr[i];
    red[tid] = s; __syncthreads();
    for (int o = 128; o > 0; o >>= 1) { if (tid < o) red[tid] += red[tid + o]; __syncthreads(); }
    float mean = red[0] / (float)DM;
    __syncthreads();

    float v = 0.f;
    for (int i = tid; i < DM; i += 256) { float d = xr[i] - mean; v += d * d; }
    red[tid] = v; __syncthreads();
    for (int o = 128; o > 0; o >>= 1) { if (tid < o) red[tid] += red[tid + o]; __syncthreads(); }
    float r = rsqrtf(red[0] / (float)DM + 1e-5f);

    for (int i = tid; i < DM; i += 256) {
        float y = scale[i] * r * (xr[i] - mean) + offset[i];
        split_store(y, xh, xl, (size_t)row * DM + i);
    }
}

// ---------------------------------------------------------------------------
// Transpose + hi/lo convert v2: 64x64 tiles, float4 loads, bf162 stores
// ---------------------------------------------------------------------------
__global__ void transcvt_kernel(const float* __restrict__ in, int R, int C,
                                bf16* __restrict__ oh, bf16* __restrict__ ol)
{
    __shared__ float t[64][65];
    int c0 = blockIdx.x * 64;
    int r0 = blockIdx.y * 64;
    int tid = threadIdx.x;
    #pragma unroll
    for (int p = 0; p < 4; p++) {
        int f = tid + p * 256;
        int row = f >> 4, c4 = (f & 15) * 4;
        float4 v = *(const float4*)(in + (size_t)(r0 + row) * C + c0 + c4);
        t[row][c4 + 0] = v.x; t[row][c4 + 1] = v.y;
        t[row][c4 + 2] = v.z; t[row][c4 + 3] = v.w;
    }
    __syncthreads();
    #pragma unroll
    for (int p = 0; p < 8; p++) {
        int w = tid + p * 256;
        int c = w >> 5, rp = (w & 31) * 2;
        float v0 = t[rp][c], v1 = t[rp + 1][c];
        size_t idx = (size_t)(c0 + c) * R + r0 + rp;
        bf16 h0 = __float2bfloat16(v0), h1 = __float2bfloat16(v1);
        __nv_bfloat162 hp; hp.x = h0; hp.y = h1;
        __nv_bfloat162 lp;
        lp.x = __float2bfloat16(v0 - __bfloat162float(h0));
        lp.y = __float2bfloat16(v1 - __bfloat162float(h1));
        *(__nv_bfloat162*)(oh + idx) = hp;
        *(__nv_bfloat162*)(ol + idx) = lp;
    }
}

// ---------------------------------------------------------------------------
// Causal softmax: row cached in smem, zero-fill to 128-block end
// ---------------------------------------------------------------------------
__global__ void softmax_kernel(const float* __restrict__ logits,
                               const float* __restrict__ attn_bias,
                               bf16* __restrict__ wh, bf16* __restrict__ wl)
{
    __shared__ float rowbuf[SEQ];
    __shared__ float red[256];
    int t = blockIdx.x;
    int h = blockIdx.y;
    int tid = threadIdx.x;
    size_t base = ((size_t)h * SEQ + t) * SEQ;
    const float* brow = attn_bias + (size_t)t * SEQ;
    int n = t + 1;
    int blockend = ((t >> 7) + 1) << 7;

    float m = -INFINITY;
    for (int T = tid; T < n; T += 256) {
        float l = logits[base + T] + brow[T];
        rowbuf[T] = l;
        m = fmaxf(m, l);
    }
    red[tid] = m; __syncthreads();
    for (int o = 128; o > 0; o >>= 1) { if (tid < o) red[tid] = fmaxf(red[tid], red[tid + o]); __syncthreads(); }
    m = red[0]; __syncthreads();

    float s = 0.f;
    for (int T = tid; T < n; T += 256) {
        float e = expf(rowbuf[T] - m);
        rowbuf[T] = e;
        s += e;
    }
    red[tid] = s; __syncthreads();
    for (int o = 128; o > 0; o >>= 1) { if (tid < o) red[tid] += red[tid + o]; __syncthreads(); }
    float inv = 1.0f / red[0];

    for (int T = tid; T < n; T += 256)
        split_store(rowbuf[T] * inv, wh, wl, base + T);
    for (int T = n + tid; T < blockend; T += 256) {
        wh[base + T] = __float2bfloat16(0.f);
        wl[base + T] = __float2bfloat16(0.f);
    }
}

// ---------------------------------------------------------------------------
// Launcher
// ---------------------------------------------------------------------------
extern "C" void kernel_launch(void* const* d_in, const int* in_sizes, int n_in,
                              void* d_out, int out_size)
{
    const float* x         = (const float*)d_in[0];
    const float* attn_bias = (const float*)d_in[1];
    const float* ln_scale  = (const float*)d_in[2];
    const float* ln_offset = (const float*)d_in[3];
    const float* wq        = (const float*)d_in[4];
    const float* wk        = (const float*)d_in[5];
    const float* wv        = (const float*)d_in[6];
    const float* wo        = (const float*)d_in[7];
    const float* w1        = (const float*)d_in[8];
    const float* b1        = (const float*)d_in[9];
    const float* w2        = (const float*)d_in[10];
    const float* b2        = (const float*)d_in[11];
    float* out = (float*)d_out;

    cudaFuncSetAttribute(gemm_bf16x3, cudaFuncAttributeMaxDynamicSharedMemorySize, GEMM_SMEM);

    bf16 *xnh, *xnl, *qh, *ql, *kh, *kl, *vth, *vtl, *wgh, *wgl, *avh, *avl, *ffh, *ffl;
    bf16 *wqth, *wqtl, *wkth, *wktl, *wvth, *wvtl, *woth, *wotl, *w1th, *w1tl, *w2th, *w2tl;
    float *v, *logits, *attnout, *ropetab;
    cudaGetSymbolAddress((void**)&xnh, g_xnh);   cudaGetSymbolAddress((void**)&xnl, g_xnl);
    cudaGetSymbolAddress((void**)&v, g_v);
    cudaGetSymbolAddress((void**)&qh, g_qh);     cudaGetSymbolAddress((void**)&ql, g_ql);
    cudaGetSymbolAddress((void**)&kh, g_kh);     cudaGetSymbolAddress((void**)&kl, g_kl);
    cudaGetSymbolAddress((void**)&vth, g_vth);   cudaGetSymbolAddress((void**)&vtl, g_vtl);
    cudaGetSymbolAddress((void**)&logits, g_logits);
    cudaGetSymbolAddress((void**)&wgh, g_wgh);   cudaGetSymbolAddress((void**)&wgl, g_wgl);
    cudaGetSymbolAddress((void**)&avh, g_avh);   cudaGetSymbolAddress((void**)&avl, g_avl);
    cudaGetSymbolAddress((void**)&attnout, g_attnout);
    cudaGetSymbolAddress((void**)&ffh, g_ffh);   cudaGetSymbolAddress((void**)&ffl, g_ffl);
    cudaGetSymbolAddress((void**)&ropetab, g_ropetab);
    cudaGetSymbolAddress((void**)&wqth, g_wqth); cudaGetSymbolAddress((void**)&wqtl, g_wqtl);
    cudaGetSymbolAddress((void**)&wkth, g_wkth); cudaGetSymbolAddress((void**)&wktl, g_wktl);
    cudaGetSymbolAddress((void**)&wvth, g_wvth); cudaGetSymbolAddress((void**)&wvtl, g_wvtl);
    cudaGetSymbolAddress((void**)&woth, g_woth); cudaGetSymbolAddress((void**)&wotl, g_wotl);
    cudaGetSymbolAddress((void**)&w1th, g_w1th); cudaGetSymbolAddress((void**)&w1tl, g_w1tl);
    cudaGetSymbolAddress((void**)&w2th, g_w2th); cudaGetSymbolAddress((void**)&w2tl, g_w2tl);

    // rope table + weight prep
    ropetab_kernel<<<(SEQ * 32 + 255) / 256, 256>>>(ropetab);
    transcvt_kernel<<<dim3(DM / 64, DM / 64), 256>>>(wq, DM, DM, wqth, wqtl);
    transcvt_kernel<<<dim3(DM / 64, DM / 64), 256>>>(wk, DM, DM, wkth, wktl);
    transcvt_kernel<<<dim3(DM / 64, DM / 64), 256>>>(wv, DM, DM, wvth, wvtl);
    transcvt_kernel<<<dim3(DM / 64, DM / 64), 256>>>(wo, DM, DM, woth, wotl);
    transcvt_kernel<<<dim3(DFF / 64, DM / 64), 256>>>(w1, DM, DFF, w1th, w1tl);
    transcvt_kernel<<<dim3(DM / 64, DFF / 64), 256>>>(w2, DFF, DM, w2th, w2tl);

    ln_kernel<<<SEQ, 256>>>(x, ln_scale, ln_offset, xnh, xnl);

    // fused QKV (z=0:q +rope, z=1:k +rope, z=2:v fp32)
    dim3 gQKV(DM / BN, SEQ / BM, 3);
    gemm_bf16x3<<<gQKV, 256, GEMM_SMEM>>>(xnh, xnl, DM, 0, wqth, wqtl, DM, 0, DM,
                                          EPI_F32, CM_NONE, nullptr, qh, ql, DM, 0,
                                          nullptr, nullptr, 1.f,
                                          1, wkth, wktl, wvth, wvtl, kh, kl, v, ropetab);

    // v transpose: v[SEQ][DM] -> vt[DM][SEQ] hi/lo
    transcvt_kernel<<<dim3(DM / 64, SEQ / 64), 256>>>(v, SEQ, DM, vth, vtl);

    // logits[h] = q_h @ k_h^T / 16 (skip fully masked tiles)
    dim3 gLog(SEQ / BN, SEQ / BM, NH);
    gemm_bf16x3<<<gLog, 256, GEMM_SMEM>>>(qh, ql, DM, DH, kh, kl, DM, DH, DH,
                                          EPI_SCALE, CM_LOGITS, logits, nullptr, nullptr, SEQ, (unsigned long long)SEQ * SEQ,
                                          nullptr, nullptr, 0.0625f,
                                          0, nullptr, nullptr, nullptr, nullptr, nullptr, nullptr, nullptr, nullptr);

    softmax_kernel<<<dim3(SEQ, NH), 256>>>(logits, attn_bias, wgh, wgl);

    // attn_vec[h] = W_h @ v_h  (variable K)
    dim3 gAV(DH / BN, SEQ / BM, NH);
    gemm_bf16x3<<<gAV, 256, GEMM_SMEM>>>(wgh, wgl, SEQ, (unsigned long long)SEQ * SEQ,
                                         vth, vtl, SEQ, (unsigned long long)DH * SEQ, SEQ,
                                         EPI_HILO, CM_AV, nullptr, avh, avl, DM, DH,
                                         nullptr, nullptr, 1.f,
                                         0, nullptr, nullptr, nullptr, nullptr, nullptr, nullptr, nullptr, nullptr);

    dim3 gProj(DM / BN, SEQ / BM, 1);
    gemm_bf16x3<<<gProj, 256, GEMM_SMEM>>>(avh, avl, DM, 0, woth, wotl, DM, 0, DM,
                                           EPI_F32, CM_NONE, attnout, nullptr, nullptr, DM, 0,
                                           nullptr, nullptr, 1.f,
                                           0, nullptr, nullptr, nullptr, nullptr, nullptr, nullptr, nullptr, nullptr);

    dim3 gFF1(DFF / BN, SEQ / BM, 1);
    gemm_bf16x3<<<gFF1, 256, GEMM_SMEM>>>(xnh, xnl, DM, 0, w1th, w1tl, DM, 0, DM,
                                          EPI_GELU_HILO, CM_NONE, nullptr, ffh, ffl, DFF, 0,
                                          b1, nullptr, 1.f,
                                          0, nullptr, nullptr, nullptr, nullptr, nullptr, nullptr, nullptr, nullptr);

    dim3 gFF2(DM / BN, SEQ / BM, 1);
    gemm_bf16x3<<<gFF2, 256, GEMM_SMEM>>>(ffh, ffl, DFF, 0, w2th, w2tl, DFF, 0, DFF,
                                          EPI_BIAS_ADD, CM_NONE, out, nullptr, nullptr, DM, 0,
                                          b2, attnout, 1.f,
                                          0, nullptr, nullptr, nullptr, nullptr, nullptr, nullptr, nullptr, nullptr);
}

// round 7
// speedup vs baseline: 1.0722x; 1.0694x over previous
#include <cuda_runtime.h>
#include <cuda_bf16.h>
#include <math.h>
#include <stdint.h>

typedef __nv_bfloat16 bf16;

#define SEQ 2048
#define DM  4096
#define NH  16
#define DH  256
#define DFF 16384

// GEMM tiling: CTA 128x256, BK=64, 8 warps (2x4), warp tile 64x64
#define BM 128
#define BN 256
#define BK 64
#define A_TILE_B 16384
#define B_TILE_B 32768
#define BUF_B    (2 * A_TILE_B + 2 * B_TILE_B)   // 96KB
#define GEMM_SMEM (2 * BUF_B)                    // 192KB

// ---------------------------------------------------------------------------
// Device-global scratch
// ---------------------------------------------------------------------------
__device__ bf16 g_xnh[SEQ*DM], g_xnl[SEQ*DM];
__device__ float g_v[SEQ*DM];
__device__ bf16 g_qh[SEQ*DM], g_ql[SEQ*DM], g_kh[SEQ*DM], g_kl[SEQ*DM];
__device__ bf16 g_vth[(size_t)DM*SEQ], g_vtl[(size_t)DM*SEQ];
__device__ float g_logits[(size_t)NH*SEQ*SEQ];
__device__ bf16 g_wgh[(size_t)NH*SEQ*SEQ], g_wgl[(size_t)NH*SEQ*SEQ];
__device__ bf16 g_avh[SEQ*DM], g_avl[SEQ*DM];
__device__ float g_attnout[SEQ*DM];
__device__ bf16 g_ffh[(size_t)SEQ*DFF], g_ffl[(size_t)SEQ*DFF];
__device__ float g_ropetab[SEQ * 64];
__device__ bf16 g_wqth[(size_t)DM*DM],  g_wqtl[(size_t)DM*DM];
__device__ bf16 g_wkth[(size_t)DM*DM],  g_wktl[(size_t)DM*DM];
__device__ bf16 g_wvth[(size_t)DM*DM],  g_wvtl[(size_t)DM*DM];
__device__ bf16 g_woth[(size_t)DM*DM],  g_wotl[(size_t)DM*DM];
__device__ bf16 g_w1th[(size_t)DFF*DM], g_w1tl[(size_t)DFF*DM];
__device__ bf16 g_w2th[(size_t)DM*DFF], g_w2tl[(size_t)DM*DFF];

// ---------------------------------------------------------------------------
// PTX helpers
// ---------------------------------------------------------------------------
__device__ __forceinline__ uint32_t smem_u32(const void* p) {
    uint32_t r;
    asm("{ .reg .u64 t; cvta.to.shared.u64 t, %1; cvt.u32.u64 %0, t; }" : "=r"(r) : "l"(p));
    return r;
}
__device__ __forceinline__ void cp16(uint32_t dst, const void* src) {
    asm volatile("cp.async.cg.shared.global [%0], [%1], 16;" :: "r"(dst), "l"(src));
}
#define CP_COMMIT() asm volatile("cp.async.commit_group;")
#define CP_WAIT(n)  asm volatile("cp.async.wait_group %0;" :: "n"(n))

#define LDMX4(r, a) \
    asm volatile("ldmatrix.sync.aligned.m8n8.x4.shared.b16 {%0,%1,%2,%3}, [%4];" \
        : "=r"((r)[0]), "=r"((r)[1]), "=r"((r)[2]), "=r"((r)[3]) : "r"(a))

#define MMA16816(c, a, b0, b1) \
    asm volatile("mma.sync.aligned.m16n8k16.row.col.f32.bf16.bf16.f32 " \
        "{%0,%1,%2,%3}, {%4,%5,%6,%7}, {%8,%9}, {%0,%1,%2,%3};" \
        : "+f"((c)[0]), "+f"((c)[1]), "+f"((c)[2]), "+f"((c)[3]) \
        : "r"((a)[0]), "r"((a)[1]), "r"((a)[2]), "r"((a)[3]), \
          "r"(b0), "r"(b1))

__device__ __forceinline__ void split_store(float v, bf16* ph, bf16* pl, size_t idx) {
    bf16 h = __float2bfloat16(v);
    ph[idx] = h;
    pl[idx] = __float2bfloat16(v - __bfloat162float(h));
}

// Epilogues (compile-time)
#define EPI_F32       0
#define EPI_SCALE     1
#define EPI_HILO      2
#define EPI_GELU_HILO 3
#define EPI_BIAS_ADD  4
#define EPI_ROPE_HILO 5
// Causal modes (compile-time)
#define CM_NONE   0
#define CM_LOGITS 1
#define CM_AV     2

__device__ __forceinline__ float gelu_tanh(float v) {
    const float c = 0.7978845608028654f;
    float t = tanhf(c * (v + 0.044715f * v * v * v));
    return 0.5f * v * (1.0f + t);
}

// ---------------------------------------------------------------------------
// Split-bf16 tensor-core GEMM: C[M,N] = A @ B^T, template-specialized epilogue
// A[M,K] row-major hi/lo bf16; B[N,K] row-major hi/lo bf16; fp32 accumulate.
// ---------------------------------------------------------------------------
template<int EPI, int CMODE>
__global__ void __launch_bounds__(256, 1) gemm_bf16x3(
    const bf16* __restrict__ Ah, const bf16* __restrict__ Al, int lda, unsigned long long sA,
    const bf16* __restrict__ Bh, const bf16* __restrict__ Bl, int ldb, unsigned long long sB,
    int K,
    float* __restrict__ Cf, bf16* __restrict__ Ch, bf16* __restrict__ Cl,
    int ldc, unsigned long long sC,
    const float* __restrict__ bias, const float* __restrict__ addv, float scale,
    const float* __restrict__ ropetab)
{
    int bm = blockIdx.y * BM;
    int bn = blockIdx.x * BN;
    if (CMODE == CM_LOGITS && bn >= bm + BM) return;

    Ah += (size_t)blockIdx.z * sA;  Al += (size_t)blockIdx.z * sA;
    Bh += (size_t)blockIdx.z * sB;  Bl += (size_t)blockIdx.z * sB;
    size_t coff = (size_t)blockIdx.z * sC;

    extern __shared__ char smem[];
    uint32_t sb = smem_u32(smem);
    int tid = threadIdx.x;
    int wid = tid >> 5, lane = tid & 31;
    int warp_m = wid >> 2, warp_n = wid & 3;

    int a_r  = ((lane >> 3) & 1) * 8 + (lane & 7);
    int a_cb = (lane >> 4) * 16;
    int b_r  = (lane >> 4) * 8 + (lane & 7);
    int b_cb = ((lane >> 3) & 1) * 16;

    float acc[4][8][4];
    #pragma unroll
    for (int i = 0; i < 4; i++)
        #pragma unroll
        for (int j = 0; j < 8; j++)
            #pragma unroll
            for (int e = 0; e < 4; e++) acc[i][j][e] = 0.f;

#define LOAD_CHUNK(k0, bufb) do {                                              \
        _Pragma("unroll")                                                      \
        for (int t = 0; t < 4; t++) {                                          \
            int ch = tid + t * 256;                                            \
            int row = ch >> 3, c = ch & 7;                                     \
            uint32_t off = row * 128 + ((c * 16) ^ ((row * 16) & 0x70));       \
            cp16((bufb) + off,            Ah + (size_t)(bm + row) * lda + (k0) + c * 8); \
            cp16((bufb) + A_TILE_B + off, Al + (size_t)(bm + row) * lda + (k0) + c * 8); \
        }                                                                      \
        _Pragma("unroll")                                                      \
        for (int t = 0; t < 8; t++) {                                          \
            int ch = tid + t * 256;                                            \
            int row = ch >> 3, c = ch & 7;                                     \
            uint32_t off = row * 128 + ((c * 16) ^ ((row * 16) & 0x70));       \
            cp16((bufb) + 2*A_TILE_B + off,            Bh + (size_t)(bn + row) * ldb + (k0) + c * 8); \
            cp16((bufb) + 2*A_TILE_B + B_TILE_B + off, Bl + (size_t)(bn + row) * ldb + (k0) + c * 8); \
        }                                                                      \
    } while (0)

    int Keff = (CMODE == CM_AV) ? (bm + BM) : K;
    int nk = Keff / BK;

    LOAD_CHUNK(0, sb);
    CP_COMMIT();

    for (int i = 0; i < nk; i++) {
        uint32_t bufb = sb + (uint32_t)(i & 1) * BUF_B;
        if (i + 1 < nk) {
            uint32_t nb = sb + (uint32_t)((i + 1) & 1) * BUF_B;
            LOAD_CHUNK((i + 1) * BK, nb);
            CP_COMMIT();
            CP_WAIT(1);
        } else {
            CP_WAIT(0);
        }
        __syncthreads();

        #pragma unroll
        for (int ks = 0; ks < 4; ks++) {
            uint32_t ahf[4][4], alf[4][4];
            #pragma unroll
            for (int mt = 0; mt < 4; mt++) {
                int row = warp_m * 64 + mt * 16 + a_r;
                uint32_t cb = ks * 32 + a_cb;
                uint32_t off = row * 128 + (cb ^ ((row * 16) & 0x70));
                LDMX4(ahf[mt], bufb + off);
                LDMX4(alf[mt], bufb + A_TILE_B + off);
            }
            uint32_t bhf[8][2], blf[8][2];
            #pragma unroll
            for (int p = 0; p < 4; p++) {
                int row = warp_n * 64 + p * 16 + b_r;
                uint32_t cb = ks * 32 + b_cb;
                uint32_t off = row * 128 + (cb ^ ((row * 16) & 0x70));
                uint32_t r[4];
                LDMX4(r, bufb + 2 * A_TILE_B + off);
                bhf[2*p][0] = r[0]; bhf[2*p][1] = r[1];
                bhf[2*p+1][0] = r[2]; bhf[2*p+1][1] = r[3];
                LDMX4(r, bufb + 2 * A_TILE_B + B_TILE_B + off);
                blf[2*p][0] = r[0]; blf[2*p][1] = r[1];
                blf[2*p+1][0] = r[2]; blf[2*p+1][1] = r[3];
            }
            #pragma unroll
            for (int mt = 0; mt < 4; mt++)
                #pragma unroll
                for (int nt = 0; nt < 8; nt++) {
                    MMA16816(acc[mt][nt], ahf[mt], bhf[nt][0], bhf[nt][1]);
                    MMA16816(acc[mt][nt], ahf[mt], blf[nt][0], blf[nt][1]);
                    MMA16816(acc[mt][nt], alf[mt], bhf[nt][0], bhf[nt][1]);
                }
        }
        __syncthreads();
    }
#undef LOAD_CHUNK

    // Epilogue (template-pruned)
    int g = lane >> 2, tg = lane & 3;
    #pragma unroll
    for (int mt = 0; mt < 4; mt++) {
        #pragma unroll
        for (int nt = 0; nt < 8; nt++) {
            int row0 = bm + warp_m * 64 + mt * 16 + g;
            int col  = bn + warp_n * 64 + nt * 8 + tg * 2;
            float* a = acc[mt][nt];
            #pragma unroll
            for (int half = 0; half < 2; half++) {
                int row = row0 + half * 8;
                float v0 = a[half * 2 + 0], v1 = a[half * 2 + 1];
                size_t idx = coff + (size_t)row * ldc + col;
                if (EPI == EPI_F32) {
                    *(float2*)(Cf + idx) = make_float2(v0, v1);
                } else if (EPI == EPI_SCALE) {
                    *(float2*)(Cf + idx) = make_float2(v0 * scale, v1 * scale);
                } else if (EPI == EPI_HILO) {
                    bf16 h0 = __float2bfloat16(v0), h1 = __float2bfloat16(v1);
                    __nv_bfloat162 hp; hp.x = h0; hp.y = h1;
                    __nv_bfloat162 lp;
                    lp.x = __float2bfloat16(v0 - __bfloat162float(h0));
                    lp.y = __float2bfloat16(v1 - __bfloat162float(h1));
                    *(__nv_bfloat162*)(Ch + idx) = hp;
                    *(__nv_bfloat162*)(Cl + idx) = lp;
                } else if (EPI == EPI_GELU_HILO) {
                    float g0 = gelu_tanh(v0 + bias[col]);
                    float g1 = gelu_tanh(v1 + bias[col + 1]);
                    bf16 h0 = __float2bfloat16(g0), h1 = __float2bfloat16(g1);
                    __nv_bfloat162 hp; hp.x = h0; hp.y = h1;
                    __nv_bfloat162 lp;
                    lp.x = __float2bfloat16(g0 - __bfloat162float(h0));
                    lp.y = __float2bfloat16(g1 - __bfloat162float(h1));
                    *(__nv_bfloat162*)(Ch + idx) = hp;
                    *(__nv_bfloat162*)(Cl + idx) = lp;
                } else if (EPI == EPI_ROPE_HILO) {
                    int d = col & (DH - 1);
                    if (d < 64) {
                        float s = ropetab[row * 64 + d];
                        float c = ropetab[row * 64 + d + 1];
                        float n0 = v0 * c - v1 * s;
                        float n1 = v1 * c + v0 * s;
                        v0 = n0; v1 = n1;
                    }
                    bf16 h0 = __float2bfloat16(v0), h1 = __float2bfloat16(v1);
                    __nv_bfloat162 hp; hp.x = h0; hp.y = h1;
                    __nv_bfloat162 lp;
                    lp.x = __float2bfloat16(v0 - __bfloat162float(h0));
                    lp.y = __float2bfloat16(v1 - __bfloat162float(h1));
                    *(__nv_bfloat162*)(Ch + idx) = hp;
                    *(__nv_bfloat162*)(Cl + idx) = lp;
                } else { // EPI_BIAS_ADD
                    float2 av = *(const float2*)(addv + idx);
                    *(float2*)(Cf + idx) = make_float2(v0 + bias[col] + av.x,
                                                       v1 + bias[col + 1] + av.y);
                }
            }
        }
    }
}

// ---------------------------------------------------------------------------
// RoPE sin/cos table (fp64): tab[t*64+2i]=sin, tab[t*64+2i+1]=cos
// ---------------------------------------------------------------------------
__global__ void ropetab_kernel(float* __restrict__ tab)
{
    int idx = blockIdx.x * 256 + threadIdx.x;
    if (idx >= SEQ * 32) return;
    int i = idx & 31, t = idx >> 5;
    double inv = exp(-(double)i * (9.210340371976184 / 32.0));
    double s, c;
    sincos((double)t * inv, &s, &c);
    tab[t * 64 + 2 * i]     = (float)s;
    tab[t * 64 + 2 * i + 1] = (float)c;
}

// ---------------------------------------------------------------------------
// LayerNorm -> hi/lo bf16
// ---------------------------------------------------------------------------
__global__ void ln_kernel(const float* __restrict__ x,
                          const float* __restrict__ scale,
                          const float* __restrict__ offset,
                          bf16* __restrict__ xh, bf16* __restrict__ xl)
{
    __shared__ float red[256];
    int row = blockIdx.x;
    int tid = threadIdx.x;
    const float* xr = x + (size_t)row * DM;

    float s = 0.f;
    for (int i = tid; i < DM; i += 256) s += xr[i];
    red[tid] = s; __syncthreads();
    for (int o = 128; o > 0; o >>= 1) { if (tid < o) red[tid] += red[tid + o]; __syncthreads(); }
    float mean = red[0] / (float)DM;
    __syncthreads();

    float v = 0.f;
    for (int i = tid; i < DM; i += 256) { float d = xr[i] - mean; v += d * d; }
    red[tid] = v; __syncthreads();
    for (int o = 128; o > 0; o >>= 1) { if (tid < o) red[tid] += red[tid + o]; __syncthreads(); }
    float r = rsqrtf(red[0] / (float)DM + 1e-5f);

    for (int i = tid; i < DM; i += 256) {
        float y = scale[i] * r * (xr[i] - mean) + offset[i];
        split_store(y, xh, xl, (size_t)row * DM + i);
    }
}

// ---------------------------------------------------------------------------
// Transpose + hi/lo convert v2: 64x64 tiles, float4 loads, bf162 stores
// ---------------------------------------------------------------------------
__global__ void transcvt_kernel(const float* __restrict__ in, int R, int C,
                                bf16* __restrict__ oh, bf16* __restrict__ ol)
{
    __shared__ float t[64][65];
    int c0 = blockIdx.x * 64;
    int r0 = blockIdx.y * 64;
    int tid = threadIdx.x;
    #pragma unroll
    for (int p = 0; p < 4; p++) {
        int f = tid + p * 256;
        int row = f >> 4, c4 = (f & 15) * 4;
        float4 v = *(const float4*)(in + (size_t)(r0 + row) * C + c0 + c4);
        t[row][c4 + 0] = v.x; t[row][c4 + 1] = v.y;
        t[row][c4 + 2] = v.z; t[row][c4 + 3] = v.w;
    }
    __syncthreads();
    #pragma unroll
    for (int p = 0; p < 8; p++) {
        int w = tid + p * 256;
        int c = w >> 5, rp = (w & 31) * 2;
        float v0 = t[rp][c], v1 = t[rp + 1][c];
        size_t idx = (size_t)(c0 + c) * R + r0 + rp;
        bf16 h0 = __float2bfloat16(v0), h1 = __float2bfloat16(v1);
        __nv_bfloat162 hp; hp.x = h0; hp.y = h1;
        __nv_bfloat162 lp;
        lp.x = __float2bfloat16(v0 - __bfloat162float(h0));
        lp.y = __float2bfloat16(v1 - __bfloat162float(h1));
        *(__nv_bfloat162*)(oh + idx) = hp;
        *(__nv_bfloat162*)(ol + idx) = lp;
    }
}

// ---------------------------------------------------------------------------
// Causal softmax: row cached in smem, zero-fill to 128-block end
// ---------------------------------------------------------------------------
__global__ void softmax_kernel(const float* __restrict__ logits,
                               const float* __restrict__ attn_bias,
                               bf16* __restrict__ wh, bf16* __restrict__ wl)
{
    __shared__ float rowbuf[SEQ];
    __shared__ float red[256];
    int t = blockIdx.x;
    int h = blockIdx.y;
    int tid = threadIdx.x;
    size_t base = ((size_t)h * SEQ + t) * SEQ;
    const float* brow = attn_bias + (size_t)t * SEQ;
    int n = t + 1;
    int blockend = ((t >> 7) + 1) << 7;

    float m = -INFINITY;
    for (int T = tid; T < n; T += 256) {
        float l = logits[base + T] + brow[T];
        rowbuf[T] = l;
        m = fmaxf(m, l);
    }
    red[tid] = m; __syncthreads();
    for (int o = 128; o > 0; o >>= 1) { if (tid < o) red[tid] = fmaxf(red[tid], red[tid + o]); __syncthreads(); }
    m = red[0]; __syncthreads();

    float s = 0.f;
    for (int T = tid; T < n; T += 256) {
        float e = expf(rowbuf[T] - m);
        rowbuf[T] = e;
        s += e;
    }
    red[tid] = s; __syncthreads();
    for (int o = 128; o > 0; o >>= 1) { if (tid < o) red[tid] += red[tid + o]; __syncthreads(); }
    float inv = 1.0f / red[0];

    for (int T = tid; T < n; T += 256)
        split_store(rowbuf[T] * inv, wh, wl, base + T);
    for (int T = n + tid; T < blockend; T += 256) {
        wh[base + T] = __float2bfloat16(0.f);
        wl[base + T] = __float2bfloat16(0.f);
    }
}

// ---------------------------------------------------------------------------
// Launcher
// ---------------------------------------------------------------------------
extern "C" void kernel_launch(void* const* d_in, const int* in_sizes, int n_in,
                              void* d_out, int out_size)
{
    const float* x         = (const float*)d_in[0];
    const float* attn_bias = (const float*)d_in[1];
    const float* ln_scale  = (const float*)d_in[2];
    const float* ln_offset = (const float*)d_in[3];
    const float* wq        = (const float*)d_in[4];
    const float* wk        = (const float*)d_in[5];
    const float* wv        = (const float*)d_in[6];
    const float* wo        = (const float*)d_in[7];
    const float* w1        = (const float*)d_in[8];
    const float* b1        = (const float*)d_in[9];
    const float* w2        = (const float*)d_in[10];
    const float* b2        = (const float*)d_in[11];
    float* out = (float*)d_out;

    cudaFuncSetAttribute(gemm_bf16x3<EPI_F32, CM_NONE>,       cudaFuncAttributeMaxDynamicSharedMemorySize, GEMM_SMEM);
    cudaFuncSetAttribute(gemm_bf16x3<EPI_ROPE_HILO, CM_NONE>, cudaFuncAttributeMaxDynamicSharedMemorySize, GEMM_SMEM);
    cudaFuncSetAttribute(gemm_bf16x3<EPI_SCALE, CM_LOGITS>,   cudaFuncAttributeMaxDynamicSharedMemorySize, GEMM_SMEM);
    cudaFuncSetAttribute(gemm_bf16x3<EPI_HILO, CM_AV>,        cudaFuncAttributeMaxDynamicSharedMemorySize, GEMM_SMEM);
    cudaFuncSetAttribute(gemm_bf16x3<EPI_GELU_HILO, CM_NONE>, cudaFuncAttributeMaxDynamicSharedMemorySize, GEMM_SMEM);
    cudaFuncSetAttribute(gemm_bf16x3<EPI_BIAS_ADD, CM_NONE>,  cudaFuncAttributeMaxDynamicSharedMemorySize, GEMM_SMEM);

    bf16 *xnh, *xnl, *qh, *ql, *kh, *kl, *vth, *vtl, *wgh, *wgl, *avh, *avl, *ffh, *ffl;
    bf16 *wqth, *wqtl, *wkth, *wktl, *wvth, *wvtl, *woth, *wotl, *w1th, *w1tl, *w2th, *w2tl;
    float *v, *logits, *attnout, *ropetab;
    cudaGetSymbolAddress((void**)&xnh, g_xnh);   cudaGetSymbolAddress((void**)&xnl, g_xnl);
    cudaGetSymbolAddress((void**)&v, g_v);
    cudaGetSymbolAddress((void**)&qh, g_qh);     cudaGetSymbolAddress((void**)&ql, g_ql);
    cudaGetSymbolAddress((void**)&kh, g_kh);     cudaGetSymbolAddress((void**)&kl, g_kl);
    cudaGetSymbolAddress((void**)&vth, g_vth);   cudaGetSymbolAddress((void**)&vtl, g_vtl);
    cudaGetSymbolAddress((void**)&logits, g_logits);
    cudaGetSymbolAddress((void**)&wgh, g_wgh);   cudaGetSymbolAddress((void**)&wgl, g_wgl);
    cudaGetSymbolAddress((void**)&avh, g_avh);   cudaGetSymbolAddress((void**)&avl, g_avl);
    cudaGetSymbolAddress((void**)&attnout, g_attnout);
    cudaGetSymbolAddress((void**)&ffh, g_ffh);   cudaGetSymbolAddress((void**)&ffl, g_ffl);
    cudaGetSymbolAddress((void**)&ropetab, g_ropetab);
    cudaGetSymbolAddress((void**)&wqth, g_wqth); cudaGetSymbolAddress((void**)&wqtl, g_wqtl);
    cudaGetSymbolAddress((void**)&wkth, g_wkth); cudaGetSymbolAddress((void**)&wktl, g_wktl);
    cudaGetSymbolAddress((void**)&wvth, g_wvth); cudaGetSymbolAddress((void**)&wvtl, g_wvtl);
    cudaGetSymbolAddress((void**)&woth, g_woth); cudaGetSymbolAddress((void**)&wotl, g_wotl);
    cudaGetSymbolAddress((void**)&w1th, g_w1th); cudaGetSymbolAddress((void**)&w1tl, g_w1tl);
    cudaGetSymbolAddress((void**)&w2th, g_w2th); cudaGetSymbolAddress((void**)&w2tl, g_w2tl);

    // rope table + weight prep
    ropetab_kernel<<<(SEQ * 32 + 255) / 256, 256>>>(ropetab);
    transcvt_kernel<<<dim3(DM / 64, DM / 64), 256>>>(wq, DM, DM, wqth, wqtl);
    transcvt_kernel<<<dim3(DM / 64, DM / 64), 256>>>(wk, DM, DM, wkth, wktl);
    transcvt_kernel<<<dim3(DM / 64, DM / 64), 256>>>(wv, DM, DM, wvth, wvtl);
    transcvt_kernel<<<dim3(DM / 64, DM / 64), 256>>>(wo, DM, DM, woth, wotl);
    transcvt_kernel<<<dim3(DFF / 64, DM / 64), 256>>>(w1, DM, DFF, w1th, w1tl);
    transcvt_kernel<<<dim3(DM / 64, DFF / 64), 256>>>(w2, DFF, DM, w2th, w2tl);

    ln_kernel<<<SEQ, 256>>>(x, ln_scale, ln_offset, xnh, xnl);

    // Q, K (rope fused), V projections
    dim3 gProj(DM / BN, SEQ / BM, 1);
    gemm_bf16x3<EPI_ROPE_HILO, CM_NONE><<<gProj, 256, GEMM_SMEM>>>(
        xnh, xnl, DM, 0, wqth, wqtl, DM, 0, DM,
        nullptr, qh, ql, DM, 0, nullptr, nullptr, 1.f, ropetab);
    gemm_bf16x3<EPI_ROPE_HILO, CM_NONE><<<gProj, 256, GEMM_SMEM>>>(
        xnh, xnl, DM, 0, wkth, wktl, DM, 0, DM,
        nullptr, kh, kl, DM, 0, nullptr, nullptr, 1.f, ropetab);
    gemm_bf16x3<EPI_F32, CM_NONE><<<gProj, 256, GEMM_SMEM>>>(
        xnh, xnl, DM, 0, wvth, wvtl, DM, 0, DM,
        v, nullptr, nullptr, DM, 0, nullptr, nullptr, 1.f, nullptr);

    // v transpose: v[SEQ][DM] -> vt[DM][SEQ] hi/lo
    transcvt_kernel<<<dim3(DM / 64, SEQ / 64), 256>>>(v, SEQ, DM, vth, vtl);

    // logits[h] = q_h @ k_h^T / 16 (skip fully masked tiles)
    dim3 gLog(SEQ / BN, SEQ / BM, NH);
    gemm_bf16x3<EPI_SCALE, CM_LOGITS><<<gLog, 256, GEMM_SMEM>>>(
        qh, ql, DM, DH, kh, kl, DM, DH, DH,
        logits, nullptr, nullptr, SEQ, (unsigned long long)SEQ * SEQ,
        nullptr, nullptr, 0.0625f, nullptr);

    softmax_kernel<<<dim3(SEQ, NH), 256>>>(logits, attn_bias, wgh, wgl);

    // attn_vec[h] = W_h @ v_h  (variable K)
    dim3 gAV(DH / BN, SEQ / BM, NH);
    gemm_bf16x3<EPI_HILO, CM_AV><<<gAV, 256, GEMM_SMEM>>>(
        wgh, wgl, SEQ, (unsigned long long)SEQ * SEQ,
        vth, vtl, SEQ, (unsigned long long)DH * SEQ, SEQ,
        nullptr, avh, avl, DM, DH, nullptr, nullptr, 1.f, nullptr);

    gemm_bf16x3<EPI_F32, CM_NONE><<<gProj, 256, GEMM_SMEM>>>(
        avh, avl, DM, 0, woth, wotl, DM, 0, DM,
        attnout, nullptr, nullptr, DM, 0, nullptr, nullptr, 1.f, nullptr);

    dim3 gFF1(DFF / BN, SEQ / BM, 1);
    gemm_bf16x3<EPI_GELU_HILO, CM_NONE><<<gFF1, 256, GEMM_SMEM>>>(
        xnh, xnl, DM, 0, w1th, w1tl, DM, 0, DM,
        nullptr, ffh, ffl, DFF, 0, b1, nullptr, 1.f, nullptr);

    dim3 gFF2(DM / BN, SEQ / BM, 1);
    gemm_bf16x3<EPI_BIAS_ADD, CM_NONE><<<gFF2, 256, GEMM_SMEM>>>(
        ffh, ffl, DFF, 0, w2th, w2tl, DFF, 0, DFF,
        out, nullptr, nullptr, DM, 0, b2, attnout, 1.f, nullptr);
}